// round 1
// baseline (speedup 1.0000x reference)
#include <cuda_runtime.h>
#include <cstdint>

#define RR 512
#define TT 4096
#define TT4 1024
#define MM 16384
#define NNODE 2048
#define NCDF 8192
#define MAXR 64
#define XOFF (RR*TT)            /* 2097152 */
#define COFF (RR*TT)
#define YOFF (XOFF + MM*TT)     /* 69206016 */

// ---------------- scratch (device globals; no allocation) ----------------
__device__ __align__(16) unsigned short g_mov_routes[MM * MAXR]; // 2 MB
__device__ int   g_mov_cnt[MM];
__device__ int   g_node_cnt[NNODE];
__device__ int   g_node_fill[NNODE];
__device__ int   g_node_start[NNODE + 1];
__device__ int   g_node_movs[MM];
__device__ float g_node_flow[NNODE * TT];                        // 32 MB
__device__ float g_co4[NCDF];
__device__ float g_flo[NCDF];
__device__ float g_base;

// ---------------- 1: relu ----------------
__global__ void k_relu(const float* __restrict__ xr, float* __restrict__ out) {
    int i = blockIdx.x * blockDim.x + threadIdx.x;   // float4 index
    if (i < RR * TT / 4) {
        float4 v = ((const float4*)xr)[i];
        v.x = fmaxf(v.x, 0.f); v.y = fmaxf(v.y, 0.f);
        v.z = fmaxf(v.z, 0.f); v.w = fmaxf(v.w, 0.f);
        ((float4*)out)[i] = v;
    }
}

// ---------------- 2: zero counters ----------------
__global__ void k_zero() {
    int i = blockIdx.x * blockDim.x + threadIdx.x;
    if (i < NNODE) { g_node_cnt[i] = 0; g_node_fill[i] = 0; }
}

// ---------------- 3: compact A rows into per-movement route lists ----------------
__global__ void k_csr_mov(const float* __restrict__ A) {
    int warp = threadIdx.x >> 5;
    int lane = threadIdx.x & 31;
    int m = blockIdx.x * 8 + warp;
    if (m >= MM) return;
    const float* row = A + (size_t)m * RR;
    unsigned base = 0;
    #pragma unroll
    for (int it = 0; it < RR / 32; ++it) {
        int r = it * 32 + lane;
        float v = row[r];
        bool nz = v > 0.5f;
        unsigned mask = __ballot_sync(0xFFFFFFFFu, nz);
        if (nz) {
            unsigned rank = __popc(mask & ((1u << lane) - 1u));
            unsigned pos = base + rank;
            if (pos < MAXR) g_mov_routes[(size_t)m * MAXR + pos] = (unsigned short)r;
        }
        base += __popc(mask);
    }
    if (lane == 0) g_mov_cnt[m] = (int)(base < MAXR ? base : MAXR);
}

// ---------------- 4: per-node movement counts ----------------
__global__ void k_node_count(const int* __restrict__ mnode) {
    int m = blockIdx.x * blockDim.x + threadIdx.x;
    if (m < MM) atomicAdd(&g_node_cnt[mnode[m]], 1);
}

// ---------------- 5: exclusive scan (single block) ----------------
__global__ void k_scan() {
    __shared__ int b0[NNODE], b1[NNODE];
    int tid = threadIdx.x;                 // 1024 threads
    b0[tid]        = g_node_cnt[tid];
    b0[tid + 1024] = g_node_cnt[tid + 1024];
    __syncthreads();
    int* src = b0; int* dst = b1;
    for (int off = 1; off < NNODE; off <<= 1) {
        #pragma unroll
        for (int k = 0; k < 2; ++k) {
            int i = tid + k * 1024;
            int v = src[i];
            if (i >= off) v += src[i - off];
            dst[i] = v;
        }
        __syncthreads();
        int* t = src; src = dst; dst = t;
    }
    g_node_start[tid + 1]    = src[tid];
    g_node_start[tid + 1025] = src[tid + 1024];
    if (tid == 0) g_node_start[0] = 0;
}

// ---------------- 6: scatter movements into node CSR ----------------
__global__ void k_scatter(const int* __restrict__ mnode) {
    int m = blockIdx.x * blockDim.x + threadIdx.x;
    if (m < MM) {
        int n = mnode[m];
        int pos = atomicAdd(&g_node_fill[n], 1);
        g_node_movs[g_node_start[n] + pos] = m;
    }
}

// ---------------- 7: main sparse GEMM: c_pred = A @ x ----------------
// block: 512 threads = 32 mlanes x 16 t-groups(float4).  Tile: 256 movements x 64 t.
// smem: x[512][64] floats (128KB) + route lists for 256 movements (32KB) = 160KB.
__global__ void __launch_bounds__(512, 1) k_gemm(const float* __restrict__ xd,
                                                 float* __restrict__ outp) {
    extern __shared__ float smem[];
    float4* xs = (float4*)smem;                          // [512][16] float4
    unsigned short* rts = (unsigned short*)(smem + RR * 64);  // [256][64]
    int tid = threadIdx.x;
    int t0 = blockIdx.x * 64;
    int m0 = blockIdx.y * 256;

    // load x tile (full K=512, 64 t columns)
    #pragma unroll
    for (int i = tid; i < RR * 16; i += 512) {
        int r = i >> 4, tg = i & 15;
        xs[i] = ((const float4*)(xd + (size_t)r * TT + t0))[tg];
    }
    // load route lists (uint4 copy, rows are 128B each)
    {
        const uint4* srcp = (const uint4*)(g_mov_routes + (size_t)m0 * MAXR);
        uint4* dstp = (uint4*)rts;
        #pragma unroll
        for (int i = tid; i < 256 * MAXR / 8; i += 512) dstp[i] = srcp[i];
    }
    __syncthreads();

    int tg = tid & 15;
    int ml = tid >> 4;   // 0..31
    float4* cp4 = (float4*)(outp + COFF);
    #pragma unroll 1
    for (int j = 0; j < 8; ++j) {
        int mlocal = ml * 8 + j;
        int cnt = g_mov_cnt[m0 + mlocal];
        const unsigned short* row = rts + mlocal * MAXR;
        float4 a = make_float4(0.f, 0.f, 0.f, 0.f);
        for (int p = 0; p < cnt; ++p) {
            int r = row[p];
            float4 v = xs[r * 16 + tg];
            a.x += v.x; a.y += v.y; a.z += v.z; a.w += v.w;
        }
        cp4[(size_t)(m0 + mlocal) * TT4 + (t0 >> 2) + tg] = a;
    }
}

// ---------------- 8: node_flow gather from c_pred ----------------
__global__ void k_nodeflow(const float* __restrict__ outp) {
    int n = blockIdx.x;
    int tj = blockIdx.y * blockDim.x + threadIdx.x;   // float4 col 0..1023
    const float4* cp4 = (const float4*)(outp + COFF);
    int s = g_node_start[n], e = g_node_start[n + 1];
    float4 acc = make_float4(0.f, 0.f, 0.f, 0.f);
    for (int i = s; i < e; ++i) {
        int m = g_node_movs[i];
        float4 v = cp4[(size_t)m * TT4 + tj];
        acc.x += v.x; acc.y += v.y; acc.z += v.z; acc.w += v.w;
    }
    ((float4*)g_node_flow)[(size_t)n * TT4 + tj] = acc;
}

// ---------------- 9: BPR per-row constants + base reduction ----------------
__global__ void k_prep(const float* __restrict__ tf, const float* __restrict__ cap,
                       const float* __restrict__ radio) {
    __shared__ float red[1024];
    int tid = threadIdx.x;
    float local = 0.f;
    for (int c = tid; c < NCDF; c += 1024) {
        float tfr = tf[c] * radio[c];
        float ic = 1.f / cap[c];
        float ic2 = ic * ic;
        g_co4[c] = 0.15f * tfr * ic2 * ic2;
        g_flo[c] = 1e-6f * cap[c];
        local += tfr;
    }
    red[tid] = local;
    __syncthreads();
    for (int s = 512; s > 0; s >>= 1) {
        if (tid < s) red[tid] += red[tid + s];
        __syncthreads();
    }
    if (tid == 0) g_base = red[0];
}

// ---------------- 10: init y to base ----------------
__global__ void k_ybase(float* __restrict__ outp) {
    int t = blockIdx.x * blockDim.x + threadIdx.x;
    if (t < TT) outp[YOFF + t] = g_base;
}

// ---------------- 11: y partial sums ----------------
__global__ void k_y(const int* __restrict__ cdfn, float* __restrict__ outp) {
    int t = blockIdx.x * blockDim.x + threadIdx.x;   // 8 blocks x 512 = 4096
    int c0 = blockIdx.y * 1024;
    float s = 0.f;
    #pragma unroll 4
    for (int c = c0; c < c0 + 1024; ++c) {
        int nc = __ldg(&cdfn[c]);
        float f = g_node_flow[(size_t)nc * TT + t];
        float g = fmaxf(f, g_flo[c]);
        float g2 = g * g;
        s += g_co4[c] * g2 * g2;
    }
    atomicAdd(&outp[YOFF + t], s);
}

// ---------------- launch ----------------
extern "C" void kernel_launch(void* const* d_in, const int* in_sizes, int n_in,
                              void* d_out, int out_size) {
    const float* x_raw  = (const float*)d_in[0];
    const float* A      = (const float*)d_in[1];
    const float* t_free = (const float*)d_in[2];
    const float* cap    = (const float*)d_in[3];
    const float* radio  = (const float*)d_in[4];
    const int*   mnode  = (const int*)d_in[5];
    const int*   cdfn   = (const int*)d_in[6];
    float* out = (float*)d_out;

    static bool attr_set = false;
    if (!attr_set) {
        cudaFuncSetAttribute(k_gemm, cudaFuncAttributeMaxDynamicSharedMemorySize,
                             160 * 1024);
        attr_set = true;
    }

    k_relu<<<(RR * TT / 4 + 255) / 256, 256>>>(x_raw, out);
    k_zero<<<(NNODE + 255) / 256, 256>>>();
    k_csr_mov<<<MM / 8, 256>>>(A);
    k_node_count<<<MM / 256, 256>>>(mnode);
    k_scan<<<1, 1024>>>();
    k_scatter<<<MM / 256, 256>>>(mnode);

    dim3 gg(TT / 64, MM / 256);           // 64 x 64
    k_gemm<<<gg, 512, 160 * 1024>>>(out, out);

    dim3 gn(NNODE, 4);
    k_nodeflow<<<gn, 256>>>(out);

    k_prep<<<1, 1024>>>(t_free, cap, radio);
    k_ybase<<<TT / 256, 256>>>(out);
    dim3 gy(TT / 512, NCDF / 1024);       // 8 x 8
    k_y<<<gy, 512>>>(cdfn, out);
}